// round 1
// baseline (speedup 1.0000x reference)
#include <cuda_runtime.h>
#include <math.h>

// ---------------------------------------------------------------------------
// LinearAttentionLayer: B=8, N=4096, D=1024, fp32
//   Q = elu(x@Wq^T + bq)+1 ; K = elu(x@Wk^T + bk)+1 ; V = x@Wv^T + bv
//   KV[b] = K[b]^T @ V[b]              (d x e)
//   Ksum[b,d] = sum_n K[b,n,d]
//   Z[b,n] = Q[b,n,:] . (Ksum[b,:] + 1e-6)
//   out    = (Q @ KV) / Z @ Wo^T + bo
// Fusion: out = Q @ (KV @ Wo^T) / Z + bo   (row-scalar commutes)
// ---------------------------------------------------------------------------

#define BATCH 8
#define NSEQ  4096
#define DIM   1024

// Scratch (device globals: allocation-free per harness rules)
__device__ float g_Q[(size_t)BATCH * NSEQ * DIM];
__device__ float g_K[(size_t)BATCH * NSEQ * DIM];
__device__ float g_V[(size_t)BATCH * NSEQ * DIM];
__device__ float g_KV[(size_t)BATCH * DIM * DIM];
__device__ float g_M [(size_t)BATCH * DIM * DIM];
__device__ float g_Kpart[16 * BATCH * DIM];
__device__ float g_Ksum[BATCH * DIM];
__device__ float g_Z[BATCH * NSEQ];

// ---------------------------------------------------------------------------
// Generic tiled fp32 GEMM: C[M,N] (+batch z) with layout/epilogue templates.
//  OPA: 0 -> A is [M,K] row-major (k contiguous)
//       1 -> A is [K,M] row-major (m contiguous)   (i.e. computes A^T * ...)
//  OPB: 0 -> B is [N,K] row-major (k contiguous)   (i.e. ... * B^T)
//       1 -> B is [K,N] row-major (n contiguous)
//  EPI: 0 -> C = acc + bias[col]
//       1 -> C = elu(acc + bias[col]) + 1
//       2 -> C = acc / zvec[row] + bias[col]
//       3 -> C = acc
// Tile: 128x128x16, 256 threads, 8x8 per thread.
// Requires M%128==0, N%128==0, K%16==0 (true for all shapes here).
// ---------------------------------------------------------------------------
#define TBM 128
#define TBN 128
#define TBK 16
#define TTM 8
#define TTN 8

template<int OPA, int OPB, int EPI>
__global__ void __launch_bounds__(256, 2)
gemm_kernel(const float* __restrict__ A, const float* __restrict__ B,
            const float* __restrict__ bias, const float* __restrict__ zvec,
            float* __restrict__ C,
            int Mdim, int Ndim, int Kdim,
            long sA, long sB, long sC, int strideZ)
{
    __shared__ float As[TBK][TBM + 4];
    __shared__ float Bs[TBK][TBN + 4];

    const float* Ab = A + (long)blockIdx.z * sA;
    const float* Bb = B + (long)blockIdx.z * sB;
    float*       Cb = C + (long)blockIdx.z * sC;

    const int tid  = threadIdx.x;
    const int brow = blockIdx.y * TBM;
    const int bcol = blockIdx.x * TBN;
    const int tr   = (tid >> 4) * TTM;   // 0..120
    const int tc   = (tid & 15) * TTN;   // 0..120

    float acc[TTM][TTN];
    #pragma unroll
    for (int i = 0; i < TTM; i++)
        #pragma unroll
        for (int j = 0; j < TTN; j++)
            acc[i][j] = 0.0f;

    for (int k0 = 0; k0 < Kdim; k0 += TBK) {
        // ---- load A tile into As[k][m] ----
        #pragma unroll
        for (int it = 0; it < 2; it++) {
            int v = tid + it * 256;             // 0..511 float4 slots
            if (OPA == 0) {
                int r  = v >> 2;                // 0..127 (m)
                int kc = (v & 3) << 2;          // 0,4,8,12
                float4 a = *(const float4*)(Ab + (long)(brow + r) * Kdim + (k0 + kc));
                As[kc + 0][r] = a.x; As[kc + 1][r] = a.y;
                As[kc + 2][r] = a.z; As[kc + 3][r] = a.w;
            } else {
                int kk = v >> 5;                // 0..15
                int mc = (v & 31) << 2;         // 0..124
                float4 a = *(const float4*)(Ab + (long)(k0 + kk) * Mdim + (brow + mc));
                *(float4*)&As[kk][mc] = a;
            }
        }
        // ---- load B tile into Bs[k][n] ----
        #pragma unroll
        for (int it = 0; it < 2; it++) {
            int v = tid + it * 256;
            if (OPB == 0) {
                int r  = v >> 2;                // 0..127 (n)
                int kc = (v & 3) << 2;
                float4 b = *(const float4*)(Bb + (long)(bcol + r) * Kdim + (k0 + kc));
                Bs[kc + 0][r] = b.x; Bs[kc + 1][r] = b.y;
                Bs[kc + 2][r] = b.z; Bs[kc + 3][r] = b.w;
            } else {
                int kk = v >> 5;
                int nc = (v & 31) << 2;
                float4 b = *(const float4*)(Bb + (long)(k0 + kk) * Ndim + (bcol + nc));
                *(float4*)&Bs[kk][nc] = b;
            }
        }
        __syncthreads();

        #pragma unroll
        for (int kk = 0; kk < TBK; kk++) {
            float4 a0 = *(const float4*)&As[kk][tr];
            float4 a1 = *(const float4*)&As[kk][tr + 4];
            float4 b0 = *(const float4*)&Bs[kk][tc];
            float4 b1 = *(const float4*)&Bs[kk][tc + 4];
            float ar[TTM] = {a0.x, a0.y, a0.z, a0.w, a1.x, a1.y, a1.z, a1.w};
            float br[TTN] = {b0.x, b0.y, b0.z, b0.w, b1.x, b1.y, b1.z, b1.w};
            #pragma unroll
            for (int i = 0; i < TTM; i++)
                #pragma unroll
                for (int j = 0; j < TTN; j++)
                    acc[i][j] = fmaf(ar[i], br[j], acc[i][j]);
        }
        __syncthreads();
    }

    // ---- epilogue ----
    #pragma unroll
    for (int i = 0; i < TTM; i++) {
        int r = brow + tr + i;
        float zi = 0.0f;
        if (EPI == 2) zi = 1.0f / zvec[(long)blockIdx.z * strideZ + r];
        #pragma unroll
        for (int j = 0; j < TTN; j += 4) {
            float4 v = make_float4(acc[i][j], acc[i][j + 1], acc[i][j + 2], acc[i][j + 3]);
            if (EPI == 0 || EPI == 1 || EPI == 2) {
                float4 bb = *(const float4*)&bias[bcol + tc + j];
                if (EPI == 2) {
                    v.x = v.x * zi + bb.x; v.y = v.y * zi + bb.y;
                    v.z = v.z * zi + bb.z; v.w = v.w * zi + bb.w;
                } else {
                    v.x += bb.x; v.y += bb.y; v.z += bb.z; v.w += bb.w;
                }
                if (EPI == 1) {
                    v.x = (v.x > 0.0f) ? v.x + 1.0f : expf(v.x);
                    v.y = (v.y > 0.0f) ? v.y + 1.0f : expf(v.y);
                    v.z = (v.z > 0.0f) ? v.z + 1.0f : expf(v.z);
                    v.w = (v.w > 0.0f) ? v.w + 1.0f : expf(v.w);
                }
            }
            *(float4*)(Cb + (long)r * Ndim + (bcol + tc + j)) = v;
        }
    }
}

// ---------------------------------------------------------------------------
// Ksum: column sums of K per batch. Two-stage (deterministic, no atomics).
// Stage 1: grid (32, 16): each (x,y) block sums a 256-row chunk of n for
// 256 consecutive (b,d) columns.
// ---------------------------------------------------------------------------
__global__ void ksum_part_kernel(const float* __restrict__ K, float* __restrict__ part)
{
    int idx = blockIdx.x * 256 + threadIdx.x;   // 0..8191 == b*1024 + d
    int b = idx >> 10;
    int d = idx & 1023;
    const float* p = K + ((long)b * NSEQ + blockIdx.y * 256) * DIM + d;
    float s = 0.0f;
    #pragma unroll 8
    for (int n = 0; n < 256; n++) s += p[(long)n * DIM];
    part[blockIdx.y * (BATCH * DIM) + idx] = s;
}

__global__ void ksum_final_kernel(const float* __restrict__ part, float* __restrict__ Ks)
{
    int idx = blockIdx.x * 256 + threadIdx.x;   // 0..8191
    float s = 0.0f;
    #pragma unroll
    for (int c = 0; c < 16; c++) s += part[c * (BATCH * DIM) + idx];
    Ks[idx] = s;
}

// ---------------------------------------------------------------------------
// Z[b,n] = Q[b,n,:] . (Ksum[b,:] + 1e-6). One warp per row.
// ---------------------------------------------------------------------------
__global__ void z_kernel(const float* __restrict__ Q, const float* __restrict__ Ks,
                         float* __restrict__ Z)
{
    int row  = blockIdx.x * 8 + (threadIdx.x >> 5);   // 0..32767
    int lane = threadIdx.x & 31;
    int b    = row >> 12;                             // 4096 rows per batch
    const float4* q  = (const float4*)(Q + (long)row * DIM);
    const float4* ks = (const float4*)(Ks + b * DIM);
    float s = 0.0f;
    #pragma unroll
    for (int i = lane; i < DIM / 4; i += 32) {
        float4 qv = q[i];
        float4 kv = ks[i];
        s += qv.x * (kv.x + 1e-6f) + qv.y * (kv.y + 1e-6f)
           + qv.z * (kv.z + 1e-6f) + qv.w * (kv.w + 1e-6f);
    }
    #pragma unroll
    for (int o = 16; o; o >>= 1) s += __shfl_xor_sync(0xffffffffu, s, o);
    if (lane == 0) Z[row] = s;
}

// ---------------------------------------------------------------------------
extern "C" void kernel_launch(void* const* d_in, const int* in_sizes, int n_in,
                              void* d_out, int out_size)
{
    const float* x  = (const float*)d_in[0];
    const float* Wq = (const float*)d_in[1];
    const float* bq = (const float*)d_in[2];
    const float* Wk = (const float*)d_in[3];
    const float* bk = (const float*)d_in[4];
    const float* Wv = (const float*)d_in[5];
    const float* bv = (const float*)d_in[6];
    const float* Wo = (const float*)d_in[7];
    const float* bo = (const float*)d_in[8];
    float* out = (float*)d_out;

    float *Q, *K, *V, *KV, *Mm, *Kp, *Ks, *Z;
    cudaGetSymbolAddress((void**)&Q,  g_Q);
    cudaGetSymbolAddress((void**)&K,  g_K);
    cudaGetSymbolAddress((void**)&V,  g_V);
    cudaGetSymbolAddress((void**)&KV, g_KV);
    cudaGetSymbolAddress((void**)&Mm, g_M);
    cudaGetSymbolAddress((void**)&Kp, g_Kpart);
    cudaGetSymbolAddress((void**)&Ks, g_Ksum);
    cudaGetSymbolAddress((void**)&Z,  g_Z);

    const int MQ = BATCH * NSEQ;        // 32768
    dim3 blk(256);

    // 1) Q/K/V projections: [32768 x 1024] = x @ W^T + b
    dim3 gproj(DIM / TBN, MQ / TBM, 1); // (8, 256)
    gemm_kernel<0, 0, 1><<<gproj, blk>>>(x, Wq, bq, nullptr, Q, MQ, DIM, DIM, 0, 0, 0, 0);
    gemm_kernel<0, 0, 1><<<gproj, blk>>>(x, Wk, bk, nullptr, K, MQ, DIM, DIM, 0, 0, 0, 0);
    gemm_kernel<0, 0, 0><<<gproj, blk>>>(x, Wv, bv, nullptr, V, MQ, DIM, DIM, 0, 0, 0, 0);

    // 2) Ksum (two-stage, deterministic)
    ksum_part_kernel <<<dim3(32, 16), blk>>>(K, Kp);
    ksum_final_kernel<<<dim3(32, 1),  blk>>>(Kp, Ks);

    // 3) KV[b] = K[b]^T @ V[b]   : [1024 x 1024], k = 4096
    gemm_kernel<1, 1, 3><<<dim3(DIM / TBN, DIM / TBM, BATCH), blk>>>(
        K, V, nullptr, nullptr, KV, DIM, DIM, NSEQ,
        (long)NSEQ * DIM, (long)NSEQ * DIM, (long)DIM * DIM, 0);

    // 4) M[b] = KV[b] @ Wo^T     : [1024 x 1024], k = 1024 (Wo shared: strideB = 0)
    gemm_kernel<0, 0, 3><<<dim3(DIM / TBN, DIM / TBM, BATCH), blk>>>(
        KV, Wo, nullptr, nullptr, Mm, DIM, DIM, DIM,
        (long)DIM * DIM, 0, (long)DIM * DIM, 0);

    // 5) Z
    z_kernel<<<MQ / 8, blk>>>(Q, Ks, Z);

    // 6) out[b] = Q[b] @ M[b] / Z + bo   : [4096 x 1024] per batch
    gemm_kernel<0, 1, 2><<<dim3(DIM / TBN, NSEQ / TBM, BATCH), blk>>>(
        Q, Mm, bo, Z, out, NSEQ, DIM, DIM,
        (long)NSEQ * DIM, (long)DIM * DIM, (long)NSEQ * DIM, NSEQ);
}

// round 11
// speedup vs baseline: 2.3880x; 2.3880x over previous
#include <cuda_runtime.h>
#include <math.h>
#include <stdint.h>

// ---------------------------------------------------------------------------
// LinearAttentionLayer: B=8, N=4096, D=1024, fp32 in/out, tf32 tensor GEMMs.
//   Q = elu(x@Wq^T + bq)+1 ; K = elu(x@Wk^T + bk)+1 ; V = x@Wv^T + bv
//   KV[b] = K[b]^T @ V[b] ;  Ksum[b,d] = sum_n K[b,n,d]
//   Z[b,n] = Q[b,n,:] . (Ksum[b,:] + 1e-6)
//   out = Q @ (KV @ Wo^T) / Z + bo      (row-scalar commutes through Wo)
//
// R5 fix: operands pre-rounded to tf32 with cvt.rna (round-to-nearest) before
// SMEM. mma.sync's implicit truncation is biased (-0.5 ulp mean) and the
// 4-deep tf32 chain accumulated ~1.2e-3 coherent error; RNA zeroes the bias.
// ---------------------------------------------------------------------------

#define BATCH 8
#define NSEQ  4096
#define DIM   1024

__device__ float g_Q[(size_t)BATCH * NSEQ * DIM];
__device__ float g_K[(size_t)BATCH * NSEQ * DIM];
__device__ float g_V[(size_t)BATCH * NSEQ * DIM];
__device__ float g_KV[(size_t)BATCH * DIM * DIM];
__device__ float g_M [(size_t)BATCH * DIM * DIM];
__device__ float g_Kpart[16 * BATCH * DIM];
__device__ float g_Ksum[BATCH * DIM];
__device__ float g_Z[BATCH * NSEQ];

#define TBM 128
#define TBN 128
#define TBK 16
#define SSTR 136

__device__ __forceinline__ float tf32_rna(float x)
{
    float y;
    asm("cvt.rna.tf32.f32 %0, %1;" : "=f"(y) : "f"(x));
    return y;
}

__device__ __forceinline__ float4 tf32_rna4(float4 v)
{
    v.x = tf32_rna(v.x); v.y = tf32_rna(v.y);
    v.z = tf32_rna(v.z); v.w = tf32_rna(v.w);
    return v;
}

__device__ __forceinline__ void mma_tf32(float (&d)[4], const uint32_t (&a)[4],
                                         const uint32_t (&b)[2])
{
    asm volatile(
        "mma.sync.aligned.m16n8k8.row.col.f32.tf32.tf32.f32 "
        "{%0,%1,%2,%3}, {%4,%5,%6,%7}, {%8,%9}, {%0,%1,%2,%3};"
        : "+f"(d[0]), "+f"(d[1]), "+f"(d[2]), "+f"(d[3])
        : "r"(a[0]), "r"(a[1]), "r"(a[2]), "r"(a[3]), "r"(b[0]), "r"(b[1]));
}

template<int OPA, int OPB, int EPI>
__global__ void __launch_bounds__(256)
gemm_tf32(const float* __restrict__ A, const float* __restrict__ B,
          const float* __restrict__ bias, const float* __restrict__ zvec,
          float* __restrict__ C,
          int Mdim, int Ndim, int Kdim,
          long sA, long sB, long sC, int strideZ)
{
    __shared__ float As[2][TBK][SSTR];
    __shared__ float Bs[2][TBK][SSTR];

    const float* Ab = A + (long)blockIdx.z * sA;
    const float* Bb = B + (long)blockIdx.z * sB;
    float*       Cb = C + (long)blockIdx.z * sC;

    const int tid  = threadIdx.x;
    const int lane = tid & 31;
    const int warp = tid >> 5;
    const int wr   = warp >> 1;          // 0..3
    const int wc   = warp & 1;           // 0..1
    const int wm   = wr * 32;
    const int wn   = wc * 64;
    const int row  = lane >> 2;          // 0..7
    const int qc   = lane & 3;           // 0..3

    const int brow = blockIdx.y * TBM;
    const int bcol = blockIdx.x * TBN;

    float acc[2][8][4];
    #pragma unroll
    for (int i = 0; i < 2; i++)
        #pragma unroll
        for (int j = 0; j < 8; j++)
            #pragma unroll
            for (int t = 0; t < 4; t++)
                acc[i][j][t] = 0.0f;

    float4 regA[2], regB[2];

    // ---- gmem tile -> staging regs ----
    auto load_tile = [&](int k0) {
        #pragma unroll
        for (int it = 0; it < 2; it++) {
            int v = tid + it * 256;
            if (OPA == 0) {
                int r = v >> 2, kc = (v & 3) << 2;
                regA[it] = *(const float4*)(Ab + (long)(brow + r) * Kdim + (k0 + kc));
            } else {
                int kk = v >> 5, mc = (v & 31) << 2;
                regA[it] = *(const float4*)(Ab + (long)(k0 + kk) * Mdim + (brow + mc));
            }
            if (OPB == 0) {
                int r = v >> 2, kc = (v & 3) << 2;
                regB[it] = *(const float4*)(Bb + (long)(bcol + r) * Kdim + (k0 + kc));
            } else {
                int kk = v >> 5, nc = (v & 31) << 2;
                regB[it] = *(const float4*)(Bb + (long)(k0 + kk) * Ndim + (bcol + nc));
            }
        }
    };

    // ---- staging regs -> smem buffer (rounded to tf32, RNA) ----
    auto store_tile = [&](int buf) {
        #pragma unroll
        for (int it = 0; it < 2; it++) {
            int v = tid + it * 256;
            float4 ra = tf32_rna4(regA[it]);
            float4 rb = tf32_rna4(regB[it]);
            if (OPA == 0) {
                int r = v >> 2, kc = (v & 3) << 2;
                As[buf][kc + 0][r] = ra.x; As[buf][kc + 1][r] = ra.y;
                As[buf][kc + 2][r] = ra.z; As[buf][kc + 3][r] = ra.w;
            } else {
                int kk = v >> 5, mc = (v & 31) << 2;
                *(float4*)&As[buf][kk][mc] = ra;
            }
            if (OPB == 0) {
                int r = v >> 2, kc = (v & 3) << 2;
                Bs[buf][kc + 0][r] = rb.x; Bs[buf][kc + 1][r] = rb.y;
                Bs[buf][kc + 2][r] = rb.z; Bs[buf][kc + 3][r] = rb.w;
            } else {
                int kk = v >> 5, nc = (v & 31) << 2;
                *(float4*)&Bs[buf][kk][nc] = rb;
            }
        }
    };

    // ---- compute one TBK=16 buffer (two k8 sub-steps) ----
    auto compute = [&](int buf) {
        #pragma unroll
        for (int kk = 0; kk < 2; kk++) {
            const int kb = kk * 8;
            uint32_t af[2][4];
            uint32_t bf[8][2];
            #pragma unroll
            for (int i = 0; i < 2; i++) {
                int m0 = wm + i * 16;
                af[i][0] = __float_as_uint(As[buf][kb + qc    ][m0 + row    ]);
                af[i][1] = __float_as_uint(As[buf][kb + qc    ][m0 + row + 8]);
                af[i][2] = __float_as_uint(As[buf][kb + qc + 4][m0 + row    ]);
                af[i][3] = __float_as_uint(As[buf][kb + qc + 4][m0 + row + 8]);
            }
            #pragma unroll
            for (int j = 0; j < 8; j++) {
                int n0 = wn + j * 8;
                bf[j][0] = __float_as_uint(Bs[buf][kb + qc    ][n0 + row]);
                bf[j][1] = __float_as_uint(Bs[buf][kb + qc + 4][n0 + row]);
            }
            #pragma unroll
            for (int i = 0; i < 2; i++)
                #pragma unroll
                for (int j = 0; j < 8; j++)
                    mma_tf32(acc[i][j], af[i], bf[j]);
        }
    };

    const int nsteps = Kdim / TBK;
    load_tile(0);
    store_tile(0);
    __syncthreads();

    int buf = 0;
    for (int s = 0; s < nsteps; s++) {
        if (s + 1 < nsteps) load_tile((s + 1) * TBK);
        compute(buf);
        if (s + 1 < nsteps) {
            store_tile(buf ^ 1);
            __syncthreads();
            buf ^= 1;
        }
    }

    // ---- epilogue ----
    #pragma unroll
    for (int i = 0; i < 2; i++) {
        int r0 = brow + wm + i * 16 + row;
        int r1 = r0 + 8;
        float z0 = 1.0f, z1 = 1.0f;
        if (EPI == 2) {
            z0 = 1.0f / zvec[(long)blockIdx.z * strideZ + r0];
            z1 = 1.0f / zvec[(long)blockIdx.z * strideZ + r1];
        }
        #pragma unroll
        for (int j = 0; j < 8; j++) {
            int nb = bcol + wn + j * 8 + qc * 2;
            float v0 = acc[i][j][0], v1 = acc[i][j][1];
            float v2 = acc[i][j][2], v3 = acc[i][j][3];
            if (EPI != 3) {
                float b0 = bias[nb], b1 = bias[nb + 1];
                if (EPI == 2) {
                    v0 = v0 * z0 + b0; v1 = v1 * z0 + b1;
                    v2 = v2 * z1 + b0; v3 = v3 * z1 + b1;
                } else {
                    v0 += b0; v1 += b1; v2 += b0; v3 += b1;
                }
                if (EPI == 1) {
                    v0 = (v0 > 0.0f) ? v0 + 1.0f : expf(v0);
                    v1 = (v1 > 0.0f) ? v1 + 1.0f : expf(v1);
                    v2 = (v2 > 0.0f) ? v2 + 1.0f : expf(v2);
                    v3 = (v3 > 0.0f) ? v3 + 1.0f : expf(v3);
                }
            }
            *(float2*)(Cb + (long)r0 * Ndim + nb) = make_float2(v0, v1);
            *(float2*)(Cb + (long)r1 * Ndim + nb) = make_float2(v2, v3);
        }
    }
}

// ---------------------------------------------------------------------------
// Ksum (two-stage, deterministic, no atomics)
// ---------------------------------------------------------------------------
__global__ void ksum_part_kernel(const float* __restrict__ K, float* __restrict__ part)
{
    int idx = blockIdx.x * 256 + threadIdx.x;   // b*1024 + d
    int b = idx >> 10;
    int d = idx & 1023;
    const float* p = K + ((long)b * NSEQ + blockIdx.y * 256) * DIM + d;
    float s = 0.0f;
    #pragma unroll 8
    for (int n = 0; n < 256; n++) s += p[(long)n * DIM];
    part[blockIdx.y * (BATCH * DIM) + idx] = s;
}

__global__ void ksum_final_kernel(const float* __restrict__ part, float* __restrict__ Ks)
{
    int idx = blockIdx.x * 256 + threadIdx.x;
    float s = 0.0f;
    #pragma unroll
    for (int c = 0; c < 16; c++) s += part[c * (BATCH * DIM) + idx];
    Ks[idx] = s;
}

// ---------------------------------------------------------------------------
// Z[b,n] = Q[b,n,:] . (Ksum[b,:] + 1e-6)   (one warp per row)
// ---------------------------------------------------------------------------
__global__ void z_kernel(const float* __restrict__ Q, const float* __restrict__ Ks,
                         float* __restrict__ Z)
{
    int row  = blockIdx.x * 8 + (threadIdx.x >> 5);
    int lane = threadIdx.x & 31;
    int b    = row >> 12;
    const float4* q  = (const float4*)(Q + (long)row * DIM);
    const float4* ks = (const float4*)(Ks + b * DIM);
    float s = 0.0f;
    #pragma unroll
    for (int i = lane; i < DIM / 4; i += 32) {
        float4 qv = q[i];
        float4 kv = ks[i];
        s += qv.x * (kv.x + 1e-6f) + qv.y * (kv.y + 1e-6f)
           + qv.z * (kv.z + 1e-6f) + qv.w * (kv.w + 1e-6f);
    }
    #pragma unroll
    for (int o = 16; o; o >>= 1) s += __shfl_xor_sync(0xffffffffu, s, o);
    if (lane == 0) Z[row] = s;
}

// ---------------------------------------------------------------------------
extern "C" void kernel_launch(void* const* d_in, const int* in_sizes, int n_in,
                              void* d_out, int out_size)
{
    const float* x  = (const float*)d_in[0];
    const float* Wq = (const float*)d_in[1];
    const float* bq = (const float*)d_in[2];
    const float* Wk = (const float*)d_in[3];
    const float* bk = (const float*)d_in[4];
    const float* Wv = (const float*)d_in[5];
    const float* bv = (const float*)d_in[6];
    const float* Wo = (const float*)d_in[7];
    const float* bo = (const float*)d_in[8];
    float* out = (float*)d_out;

    float *Q, *K, *V, *KV, *Mm, *Kp, *Ks, *Z;
    cudaGetSymbolAddress((void**)&Q,  g_Q);
    cudaGetSymbolAddress((void**)&K,  g_K);
    cudaGetSymbolAddress((void**)&V,  g_V);
    cudaGetSymbolAddress((void**)&KV, g_KV);
    cudaGetSymbolAddress((void**)&Mm, g_M);
    cudaGetSymbolAddress((void**)&Kp, g_Kpart);
    cudaGetSymbolAddress((void**)&Ks, g_Ksum);
    cudaGetSymbolAddress((void**)&Z,  g_Z);

    const int MQ = BATCH * NSEQ;        // 32768
    dim3 blk(256);

    // 1) Projections: [32768 x 1024] = x @ W^T + b  (tf32, RNA)
    dim3 gproj(DIM / TBN, MQ / TBM, 1);
    gemm_tf32<0, 0, 1><<<gproj, blk>>>(x, Wq, bq, nullptr, Q, MQ, DIM, DIM, 0, 0, 0, 0);
    gemm_tf32<0, 0, 1><<<gproj, blk>>>(x, Wk, bk, nullptr, K, MQ, DIM, DIM, 0, 0, 0, 0);
    gemm_tf32<0, 0, 0><<<gproj, blk>>>(x, Wv, bv, nullptr, V, MQ, DIM, DIM, 0, 0, 0, 0);

    // 2) Ksum (exact fp32)
    ksum_part_kernel <<<dim3(32, 16), blk>>>(K, Kp);
    ksum_final_kernel<<<dim3(32, 1),  blk>>>(Kp, Ks);

    // 3) KV[b] = K[b]^T @ V[b] : [1024 x 1024], k = 4096
    gemm_tf32<1, 1, 3><<<dim3(DIM / TBN, DIM / TBM, BATCH), blk>>>(
        K, V, nullptr, nullptr, KV, DIM, DIM, NSEQ,
        (long)NSEQ * DIM, (long)NSEQ * DIM, (long)DIM * DIM, 0);

    // 4) M[b] = KV[b] @ Wo^T : [1024 x 1024], k = 1024 (Wo shared, strideB=0)
    gemm_tf32<0, 0, 3><<<dim3(DIM / TBN, DIM / TBM, BATCH), blk>>>(
        KV, Wo, nullptr, nullptr, Mm, DIM, DIM, DIM,
        (long)DIM * DIM, 0, (long)DIM * DIM, 0);

    // 5) Z
    z_kernel<<<MQ / 8, blk>>>(Q, Ks, Z);

    // 6) out[b] = Q[b] @ M[b] / Z + bo : [4096 x 1024] per batch
    gemm_tf32<0, 1, 2><<<dim3(DIM / TBN, NSEQ / TBM, BATCH), blk>>>(
        Q, Mm, bo, Z, out, NSEQ, DIM, DIM,
        (long)NSEQ * DIM, (long)DIM * DIM, (long)NSEQ * DIM, NSEQ);
}

// round 13
// speedup vs baseline: 3.0442x; 1.2748x over previous
#include <cuda_runtime.h>
#include <math.h>
#include <stdint.h>

// ---------------------------------------------------------------------------
// LinearAttentionLayer: B=8, N=4096, D=1024, fp32 in/out, tf32 tensor GEMMs.
//   out = Q @ (KV @ Wo^T) / Z + bo   (division commutes through Wo)
//
// R12: cp.async 2-stage pipelined mainloop; RNA rounding hoisted out of the
// loop (prepass rounds x/W once; producer epilogues round Q/K/V/KV/M).
// ---------------------------------------------------------------------------

#define BATCH 8
#define NSEQ  4096
#define DIM   1024

__device__ float g_X[(size_t)BATCH * NSEQ * DIM];
__device__ float g_Wq[DIM * DIM];
__device__ float g_Wk[DIM * DIM];
__device__ float g_Wv[DIM * DIM];
__device__ float g_Wo[DIM * DIM];
__device__ float g_Q[(size_t)BATCH * NSEQ * DIM];
__device__ float g_K[(size_t)BATCH * NSEQ * DIM];
__device__ float g_V[(size_t)BATCH * NSEQ * DIM];
__device__ float g_KV[(size_t)BATCH * DIM * DIM];
__device__ float g_M [(size_t)BATCH * DIM * DIM];
__device__ float g_Kpart[16 * BATCH * DIM];
__device__ float g_Ksum[BATCH * DIM];
__device__ float g_Z[BATCH * NSEQ];

#define TBM 128
#define TBN 128
#define TBK 16
#define RM_STR 20    // row-major smem stride: 20*row+qc mod 32 -> conflict-free
#define KM_STR 136   // k-major smem stride: 136k+m pattern conflict-free
#define STG_FLOATS 2560  // max(128*RM_STR=2560, 16*KM_STR=2176)

__device__ __forceinline__ float tf32_rna(float x)
{
    float y;
    asm("cvt.rna.tf32.f32 %0, %1;" : "=f"(y) : "f"(x));
    return y;
}

__device__ __forceinline__ void cp16(float* smem_dst, const float* gsrc)
{
    uint32_t d = (uint32_t)__cvta_generic_to_shared(smem_dst);
    asm volatile("cp.async.cg.shared.global [%0], [%1], 16;\n"
                 :: "r"(d), "l"(gsrc));
}
#define CP_COMMIT() asm volatile("cp.async.commit_group;\n" ::: "memory")
#define CP_WAIT1()  asm volatile("cp.async.wait_group 1;\n" ::: "memory")

__device__ __forceinline__ void mma_tf32(float (&d)[4], const uint32_t (&a)[4],
                                         const uint32_t (&b)[2])
{
    asm volatile(
        "mma.sync.aligned.m16n8k8.row.col.f32.tf32.tf32.f32 "
        "{%0,%1,%2,%3}, {%4,%5,%6,%7}, {%8,%9}, {%0,%1,%2,%3};"
        : "+f"(d[0]), "+f"(d[1]), "+f"(d[2]), "+f"(d[3])
        : "r"(a[0]), "r"(a[1]), "r"(a[2]), "r"(a[3]), "r"(b[0]), "r"(b[1]));
}

// OPA/OPB: 0 -> operand [rows,K] k-contig (rm smem), 1 -> [K,cols] col-contig (km smem)
// EPI: 0 +bias ; 1 elu(+bias)+1 ; 2 *1/z+bias ; 3 none.  RND: tf32-round stores.
template<int OPA, int OPB, int EPI, int RND>
__global__ void __launch_bounds__(256, 2)
gemm_tf32(const float* __restrict__ A, const float* __restrict__ B,
          const float* __restrict__ bias, const float* __restrict__ zvec,
          float* __restrict__ C,
          int Mdim, int Ndim, int Kdim,
          long sA, long sB, long sC, int strideZ)
{
    __shared__ float As[2][STG_FLOATS];
    __shared__ float Bs[2][STG_FLOATS];

    const float* Ab = A + (long)blockIdx.z * sA;
    const float* Bb = B + (long)blockIdx.z * sB;
    float*       Cb = C + (long)blockIdx.z * sC;

    const int tid  = threadIdx.x;
    const int lane = tid & 31;
    const int warp = tid >> 5;
    const int wm   = (warp >> 1) * 32;
    const int wn   = (warp & 1) * 64;
    const int row  = lane >> 2;          // 0..7
    const int qc   = lane & 3;           // 0..3

    const int brow = blockIdx.y * TBM;
    const int bcol = blockIdx.x * TBN;

    float acc[2][8][4];
    #pragma unroll
    for (int i = 0; i < 2; i++)
        #pragma unroll
        for (int j = 0; j < 8; j++)
            #pragma unroll
            for (int t = 0; t < 4; t++)
                acc[i][j][t] = 0.0f;

    // ---- async load one stage (512 16B chunks per operand) ----
    auto load_stage = [&](int s, int k0) {
        float* as = As[s];
        float* bs = Bs[s];
        #pragma unroll
        for (int it = 0; it < 2; it++) {
            int c = tid + it * 256;              // 0..511
            if (OPA == 0) {
                int r = c >> 2, kc = (c & 3) << 2;
                cp16(&as[r * RM_STR + kc], Ab + (long)(brow + r) * Kdim + (k0 + kc));
            } else {
                int kk = c >> 5, mc = (c & 31) << 2;
                cp16(&as[kk * KM_STR + mc], Ab + (long)(k0 + kk) * Mdim + (brow + mc));
            }
            if (OPB == 0) {
                int r = c >> 2, kc = (c & 3) << 2;
                cp16(&bs[r * RM_STR + kc], Bb + (long)(bcol + r) * Kdim + (k0 + kc));
            } else {
                int kk = c >> 5, nc = (c & 31) << 2;
                cp16(&bs[kk * KM_STR + nc], Bb + (long)(k0 + kk) * Ndim + (bcol + nc));
            }
        }
    };

    auto compute = [&](int s) {
        const float* as = As[s];
        const float* bs = Bs[s];
        #pragma unroll
        for (int kk = 0; kk < 2; kk++) {
            const int kb = kk * 8;
            uint32_t af[2][4];
            uint32_t bf[8][2];
            #pragma unroll
            for (int i = 0; i < 2; i++) {
                int m0 = wm + i * 16;
                if (OPA == 0) {
                    af[i][0] = __float_as_uint(as[(m0 + row    ) * RM_STR + kb + qc    ]);
                    af[i][1] = __float_as_uint(as[(m0 + row + 8) * RM_STR + kb + qc    ]);
                    af[i][2] = __float_as_uint(as[(m0 + row    ) * RM_STR + kb + qc + 4]);
                    af[i][3] = __float_as_uint(as[(m0 + row + 8) * RM_STR + kb + qc + 4]);
                } else {
                    af[i][0] = __float_as_uint(as[(kb + qc    ) * KM_STR + m0 + row    ]);
                    af[i][1] = __float_as_uint(as[(kb + qc    ) * KM_STR + m0 + row + 8]);
                    af[i][2] = __float_as_uint(as[(kb + qc + 4) * KM_STR + m0 + row    ]);
                    af[i][3] = __float_as_uint(as[(kb + qc + 4) * KM_STR + m0 + row + 8]);
                }
            }
            #pragma unroll
            for (int j = 0; j < 8; j++) {
                int n0 = wn + j * 8;
                if (OPB == 0) {
                    bf[j][0] = __float_as_uint(bs[(n0 + row) * RM_STR + kb + qc    ]);
                    bf[j][1] = __float_as_uint(bs[(n0 + row) * RM_STR + kb + qc + 4]);
                } else {
                    bf[j][0] = __float_as_uint(bs[(kb + qc    ) * KM_STR + n0 + row]);
                    bf[j][1] = __float_as_uint(bs[(kb + qc + 4) * KM_STR + n0 + row]);
                }
            }
            #pragma unroll
            for (int i = 0; i < 2; i++)
                #pragma unroll
                for (int j = 0; j < 8; j++)
                    mma_tf32(acc[i][j], af[i], bf[j]);
        }
    };

    const int nsteps = Kdim / TBK;     // >= 2 for all shapes here
    load_stage(0, 0);
    CP_COMMIT();
    load_stage(1, TBK);
    CP_COMMIT();

    for (int s = 0; s < nsteps; s++) {
        CP_WAIT1();
        __syncthreads();
        compute(s & 1);
        __syncthreads();               // buffer s&1 free before refill
        if (s + 2 < nsteps) load_stage(s & 1, (s + 2) * TBK);
        CP_COMMIT();                   // commit (possibly empty) keeps count
    }

    // ---- epilogue ----
    #pragma unroll
    for (int i = 0; i < 2; i++) {
        int r0 = brow + wm + i * 16 + row;
        int r1 = r0 + 8;
        float z0 = 1.0f, z1 = 1.0f;
        if (EPI == 2) {
            z0 = 1.0f / zvec[(long)blockIdx.z * strideZ + r0];
            z1 = 1.0f / zvec[(long)blockIdx.z * strideZ + r1];
        }
        #pragma unroll
        for (int j = 0; j < 8; j++) {
            int nb = bcol + wn + j * 8 + qc * 2;
            float v0 = acc[i][j][0], v1 = acc[i][j][1];
            float v2 = acc[i][j][2], v3 = acc[i][j][3];
            if (EPI != 3) {
                float b0 = bias[nb], b1 = bias[nb + 1];
                if (EPI == 2) {
                    v0 = v0 * z0 + b0; v1 = v1 * z0 + b1;
                    v2 = v2 * z1 + b0; v3 = v3 * z1 + b1;
                } else {
                    v0 += b0; v1 += b1; v2 += b0; v3 += b1;
                }
                if (EPI == 1) {
                    v0 = (v0 > 0.0f) ? v0 + 1.0f : expf(v0);
                    v1 = (v1 > 0.0f) ? v1 + 1.0f : expf(v1);
                    v2 = (v2 > 0.0f) ? v2 + 1.0f : expf(v2);
                    v3 = (v3 > 0.0f) ? v3 + 1.0f : expf(v3);
                }
            }
            if (RND) {
                v0 = tf32_rna(v0); v1 = tf32_rna(v1);
                v2 = tf32_rna(v2); v3 = tf32_rna(v3);
            }
            *(float2*)(Cb + (long)r0 * Ndim + nb) = make_float2(v0, v1);
            *(float2*)(Cb + (long)r1 * Ndim + nb) = make_float2(v2, v3);
        }
    }
}

// ---------------------------------------------------------------------------
// Elementwise tf32-RNA rounding prepass (x, weights)
// ---------------------------------------------------------------------------
__global__ void round_kernel(const float* __restrict__ src, float* __restrict__ dst,
                             int n4)
{
    int stride = gridDim.x * blockDim.x;
    for (int i = blockIdx.x * blockDim.x + threadIdx.x; i < n4; i += stride) {
        float4 v = ((const float4*)src)[i];
        v.x = tf32_rna(v.x); v.y = tf32_rna(v.y);
        v.z = tf32_rna(v.z); v.w = tf32_rna(v.w);
        ((float4*)dst)[i] = v;
    }
}

// ---------------------------------------------------------------------------
// Ksum (two-stage, deterministic)
// ---------------------------------------------------------------------------
__global__ void ksum_part_kernel(const float* __restrict__ K, float* __restrict__ part)
{
    int idx = blockIdx.x * 256 + threadIdx.x;   // b*1024 + d
    int b = idx >> 10;
    int d = idx & 1023;
    const float* p = K + ((long)b * NSEQ + blockIdx.y * 256) * DIM + d;
    float s = 0.0f;
    #pragma unroll 8
    for (int n = 0; n < 256; n++) s += p[(long)n * DIM];
    part[blockIdx.y * (BATCH * DIM) + idx] = s;
}

__global__ void ksum_final_kernel(const float* __restrict__ part, float* __restrict__ Ks)
{
    int idx = blockIdx.x * 256 + threadIdx.x;
    float s = 0.0f;
    #pragma unroll
    for (int c = 0; c < 16; c++) s += part[c * (BATCH * DIM) + idx];
    Ks[idx] = s;
}

// ---------------------------------------------------------------------------
// Z[b,n] = Q[b,n,:] . (Ksum[b,:] + 1e-6)
// ---------------------------------------------------------------------------
__global__ void z_kernel(const float* __restrict__ Q, const float* __restrict__ Ks,
                         float* __restrict__ Z)
{
    int row  = blockIdx.x * 8 + (threadIdx.x >> 5);
    int lane = threadIdx.x & 31;
    int b    = row >> 12;
    const float4* q  = (const float4*)(Q + (long)row * DIM);
    const float4* ks = (const float4*)(Ks + b * DIM);
    float s = 0.0f;
    #pragma unroll
    for (int i = lane; i < DIM / 4; i += 32) {
        float4 qv = q[i];
        float4 kv = ks[i];
        s += qv.x * (kv.x + 1e-6f) + qv.y * (kv.y + 1e-6f)
           + qv.z * (kv.z + 1e-6f) + qv.w * (kv.w + 1e-6f);
    }
    #pragma unroll
    for (int o = 16; o; o >>= 1) s += __shfl_xor_sync(0xffffffffu, s, o);
    if (lane == 0) Z[row] = s;
}

// ---------------------------------------------------------------------------
extern "C" void kernel_launch(void* const* d_in, const int* in_sizes, int n_in,
                              void* d_out, int out_size)
{
    const float* x  = (const float*)d_in[0];
    const float* Wq = (const float*)d_in[1];
    const float* bq = (const float*)d_in[2];
    const float* Wk = (const float*)d_in[3];
    const float* bk = (const float*)d_in[4];
    const float* Wv = (const float*)d_in[5];
    const float* bv = (const float*)d_in[6];
    const float* Wo = (const float*)d_in[7];
    const float* bo = (const float*)d_in[8];
    float* out = (float*)d_out;

    float *X, *RWq, *RWk, *RWv, *RWo, *Q, *K, *V, *KV, *Mm, *Kp, *Ks, *Z;
    cudaGetSymbolAddress((void**)&X,   g_X);
    cudaGetSymbolAddress((void**)&RWq, g_Wq);
    cudaGetSymbolAddress((void**)&RWk, g_Wk);
    cudaGetSymbolAddress((void**)&RWv, g_Wv);
    cudaGetSymbolAddress((void**)&RWo, g_Wo);
    cudaGetSymbolAddress((void**)&Q,   g_Q);
    cudaGetSymbolAddress((void**)&K,   g_K);
    cudaGetSymbolAddress((void**)&V,   g_V);
    cudaGetSymbolAddress((void**)&KV,  g_KV);
    cudaGetSymbolAddress((void**)&Mm,  g_M);
    cudaGetSymbolAddress((void**)&Kp,  g_Kpart);
    cudaGetSymbolAddress((void**)&Ks,  g_Ksum);
    cudaGetSymbolAddress((void**)&Z,   g_Z);

    const int MQ = BATCH * NSEQ;        // 32768
    dim3 blk(256);

    // 0) RNA prepass on external GEMM operands
    round_kernel<<<2048, blk>>>(x,  X,   (MQ * DIM) / 4);
    round_kernel<<<256,  blk>>>(Wq, RWq, (DIM * DIM) / 4);
    round_kernel<<<256,  blk>>>(Wk, RWk, (DIM * DIM) / 4);
    round_kernel<<<256,  blk>>>(Wv, RWv, (DIM * DIM) / 4);
    round_kernel<<<256,  blk>>>(Wo, RWo, (DIM * DIM) / 4);

    // 1) Projections (RND epilogue: outputs feed later GEMMs)
    dim3 gproj(DIM / TBN, MQ / TBM, 1);
    gemm_tf32<0, 0, 1, 1><<<gproj, blk>>>(X, RWq, bq, nullptr, Q, MQ, DIM, DIM, 0, 0, 0, 0);
    gemm_tf32<0, 0, 1, 1><<<gproj, blk>>>(X, RWk, bk, nullptr, K, MQ, DIM, DIM, 0, 0, 0, 0);
    gemm_tf32<0, 0, 0, 1><<<gproj, blk>>>(X, RWv, bv, nullptr, V, MQ, DIM, DIM, 0, 0, 0, 0);

    // 2) Ksum over rounded K (consistent with GEMM view of K)
    ksum_part_kernel <<<dim3(32, 16), blk>>>(K, Kp);
    ksum_final_kernel<<<dim3(32, 1),  blk>>>(Kp, Ks);

    // 3) KV[b] = K[b]^T @ V[b]  (k = 4096)
    gemm_tf32<1, 1, 3, 1><<<dim3(DIM / TBN, DIM / TBM, BATCH), blk>>>(
        K, V, nullptr, nullptr, KV, DIM, DIM, NSEQ,
        (long)NSEQ * DIM, (long)NSEQ * DIM, (long)DIM * DIM, 0);

    // 4) M[b] = KV[b] @ Wo^T  (k = 1024, Wo shared: strideB = 0)
    gemm_tf32<0, 0, 3, 1><<<dim3(DIM / TBN, DIM / TBM, BATCH), blk>>>(
        KV, RWo, nullptr, nullptr, Mm, DIM, DIM, DIM,
        (long)DIM * DIM, 0, (long)DIM * DIM, 0);

    // 5) Z
    z_kernel<<<MQ / 8, blk>>>(Q, Ks, Z);

    // 6) out[b] = Q[b] @ M[b] / Z + bo  (no rounding on final output)
    gemm_tf32<0, 1, 2, 0><<<dim3(DIM / TBN, NSEQ / TBM, BATCH), blk>>>(
        Q, Mm, bo, Z, out, NSEQ, DIM, DIM,
        (long)NSEQ * DIM, (long)DIM * DIM, (long)NSEQ * DIM, NSEQ);
}

// round 14
// speedup vs baseline: 3.1513x; 1.0352x over previous
#include <cuda_runtime.h>
#include <math.h>
#include <stdint.h>

// ---------------------------------------------------------------------------
// LinearAttentionLayer: B=8, N=4096, D=1024, fp32, tf32 tensor GEMMs.
// R14: all GEMMs in (rm, rm) form -> ldmatrix.x4 fragment loads (12 LDSM vs
// 48 LDS per k-step). Transposed dataflow:
//   Q  = elu(x@Wq^T+bq)+1                      [n,d]
//   Kt = elu(Wk@x^T +bk[row])+1               [d,n]
//   Vt = Wv@x^T + bv[row]                      [e,n]
//   KV[d,e] = sum_n Kt[d,n]Vt[e,n]
//   Mt[e,d] = sum_c Wo[e,c]KV[d,c]   (= M^T, M = KV@Wo^T)
//   out[n,e] = (sum_d Q[n,d]Mt[e,d]) / Z[n] + bo[e]
// ---------------------------------------------------------------------------

#define BATCH 8
#define NSEQ  4096
#define DIM   1024

__device__ float g_X[(size_t)BATCH * NSEQ * DIM];
__device__ float g_Wq[DIM * DIM];
__device__ float g_Wk[DIM * DIM];
__device__ float g_Wv[DIM * DIM];
__device__ float g_Wo[DIM * DIM];
__device__ float g_Q [(size_t)BATCH * NSEQ * DIM];
__device__ float g_Kt[(size_t)BATCH * NSEQ * DIM];
__device__ float g_Vt[(size_t)BATCH * NSEQ * DIM];
__device__ float g_KV[(size_t)BATCH * DIM * DIM];
__device__ float g_Mt[(size_t)BATCH * DIM * DIM];
__device__ float g_Ksum[BATCH * DIM];
__device__ float g_Z[BATCH * NSEQ];

#define TBM 128
#define TBN 128
#define TBK 16
#define RM_STR 20          // 20*row+qc mod 32 -> conflict-free, rows 16B-aligned
#define STG_FLOATS (128 * RM_STR)

__device__ __forceinline__ float tf32_rna(float x)
{
    float y;
    asm("cvt.rna.tf32.f32 %0, %1;" : "=f"(y) : "f"(x));
    return y;
}

__device__ __forceinline__ void cp16(float* smem_dst, const float* gsrc)
{
    uint32_t d = (uint32_t)__cvta_generic_to_shared(smem_dst);
    asm volatile("cp.async.cg.shared.global [%0], [%1], 16;\n"
                 :: "r"(d), "l"(gsrc));
}
#define CP_COMMIT() asm volatile("cp.async.commit_group;\n" ::: "memory")
#define CP_WAIT1()  asm volatile("cp.async.wait_group 1;\n" ::: "memory")

__device__ __forceinline__ void ldsm_x4(uint32_t (&r)[4], const float* p)
{
    uint32_t a = (uint32_t)__cvta_generic_to_shared(p);
    asm volatile("ldmatrix.sync.aligned.m8n8.x4.shared.b16 {%0,%1,%2,%3}, [%4];"
                 : "=r"(r[0]), "=r"(r[1]), "=r"(r[2]), "=r"(r[3]) : "r"(a));
}

__device__ __forceinline__ void mma_tf32(float (&d)[4], const uint32_t (&a)[4],
                                         const uint32_t (&b)[2])
{
    asm volatile(
        "mma.sync.aligned.m16n8k8.row.col.f32.tf32.tf32.f32 "
        "{%0,%1,%2,%3}, {%4,%5,%6,%7}, {%8,%9}, {%0,%1,%2,%3};"
        : "+f"(d[0]), "+f"(d[1]), "+f"(d[2]), "+f"(d[3])
        : "r"(a[0]), "r"(a[1]), "r"(a[2]), "r"(a[3]), "r"(b[0]), "r"(b[1]));
}

// C[M,N] = A[M,K] @ B[N,K]^T, both rm (k-contiguous).
// EPI: 0 col-bias ; 1 col-bias+elu ; 2 z-scale+col-bias ; 3 none ;
//      4 row-bias ; 5 row-bias+elu.   RND: tf32-round the stores.
template<int EPI, int RND>
__global__ void __launch_bounds__(256, 2)
gemm_tf32(const float* __restrict__ A, const float* __restrict__ B,
          const float* __restrict__ bias, const float* __restrict__ zvec,
          float* __restrict__ C,
          int Ndim, int Kdim,
          long sA, long sB, long sC, int strideZ)
{
    __shared__ float As[2][STG_FLOATS];
    __shared__ float Bs[2][STG_FLOATS];

    const float* Ab = A + (long)blockIdx.z * sA;
    const float* Bb = B + (long)blockIdx.z * sB;
    float*       Cb = C + (long)blockIdx.z * sC;

    const int tid  = threadIdx.x;
    const int lane = tid & 31;
    const int warp = tid >> 5;
    const int wm   = (warp >> 1) * 32;
    const int wn   = (warp & 1) * 64;
    const int row  = lane >> 2;          // 0..7
    const int qc   = lane & 3;           // 0..3

    const int brow = blockIdx.y * TBM;
    const int bcol = blockIdx.x * TBN;

    // ldmatrix per-lane source rows (PTX: lane l -> matrix l/8, row l%8)
    const int mat      = lane >> 3;                  // 0..3
    const int arow_off = ((mat & 1) << 3) + (lane & 7);
    const int akc      = (mat >> 1) << 2;            // 0 or 4
    const int brow_off = ((mat >> 1) << 3) + (lane & 7);
    const int bkc      = (mat & 1) << 2;             // 0 or 4

    float acc[2][8][4];
    #pragma unroll
    for (int i = 0; i < 2; i++)
        #pragma unroll
        for (int j = 0; j < 8; j++)
            #pragma unroll
            for (int t = 0; t < 4; t++)
                acc[i][j][t] = 0.0f;

    auto load_stage = [&](int s, int k0) {
        float* as = As[s];
        float* bs = Bs[s];
        #pragma unroll
        for (int it = 0; it < 2; it++) {
            int c = tid + it * 256;              // 0..511
            int r = c >> 2, kc = (c & 3) << 2;
            cp16(&as[r * RM_STR + kc], Ab + (long)(brow + r) * Kdim + (k0 + kc));
            cp16(&bs[r * RM_STR + kc], Bb + (long)(bcol + r) * Kdim + (k0 + kc));
        }
    };

    auto compute = [&](int s) {
        const float* as = As[s];
        const float* bs = Bs[s];
        #pragma unroll
        for (int kk = 0; kk < 2; kk++) {
            const int kb = kk * 8;
            uint32_t af[2][4];
            uint32_t bq4[4][4];
            #pragma unroll
            for (int i = 0; i < 2; i++)
                ldsm_x4(af[i], &as[(wm + i * 16 + arow_off) * RM_STR + kb + akc]);
            #pragma unroll
            for (int j2 = 0; j2 < 4; j2++)
                ldsm_x4(bq4[j2], &bs[(wn + j2 * 16 + brow_off) * RM_STR + kb + bkc]);
            #pragma unroll
            for (int i = 0; i < 2; i++)
                #pragma unroll
                for (int j2 = 0; j2 < 4; j2++) {
                    uint32_t b0[2] = {bq4[j2][0], bq4[j2][1]};
                    uint32_t b1[2] = {bq4[j2][2], bq4[j2][3]};
                    mma_tf32(acc[i][j2 * 2    ], af[i], b0);
                    mma_tf32(acc[i][j2 * 2 + 1], af[i], b1);
                }
        }
    };

    const int nsteps = Kdim / TBK;
    load_stage(0, 0);
    CP_COMMIT();
    load_stage(1, TBK);
    CP_COMMIT();

    for (int s = 0; s < nsteps; s++) {
        CP_WAIT1();
        __syncthreads();
        compute(s & 1);
        __syncthreads();
        if (s + 2 < nsteps) load_stage(s & 1, (s + 2) * TBK);
        CP_COMMIT();
    }

    // ---- epilogue ----
    #pragma unroll
    for (int i = 0; i < 2; i++) {
        int r0 = brow + wm + i * 16 + row;
        int r1 = r0 + 8;
        float z0 = 1.0f, z1 = 1.0f;
        if (EPI == 2) {
            z0 = 1.0f / zvec[(long)blockIdx.z * strideZ + r0];
            z1 = 1.0f / zvec[(long)blockIdx.z * strideZ + r1];
        }
        float rb0 = 0.0f, rb1 = 0.0f;
        if (EPI == 4 || EPI == 5) { rb0 = bias[r0]; rb1 = bias[r1]; }
        #pragma unroll
        for (int j = 0; j < 8; j++) {
            int nb = bcol + wn + j * 8 + qc * 2;
            float v0 = acc[i][j][0], v1 = acc[i][j][1];
            float v2 = acc[i][j][2], v3 = acc[i][j][3];
            if (EPI == 0 || EPI == 1 || EPI == 2) {
                float b0 = bias[nb], b1 = bias[nb + 1];
                if (EPI == 2) {
                    v0 = v0 * z0 + b0; v1 = v1 * z0 + b1;
                    v2 = v2 * z1 + b0; v3 = v3 * z1 + b1;
                } else {
                    v0 += b0; v1 += b1; v2 += b0; v3 += b1;
                }
            } else if (EPI == 4 || EPI == 5) {
                v0 += rb0; v1 += rb0; v2 += rb1; v3 += rb1;
            }
            if (EPI == 1 || EPI == 5) {
                v0 = (v0 > 0.0f) ? v0 + 1.0f : expf(v0);
                v1 = (v1 > 0.0f) ? v1 + 1.0f : expf(v1);
                v2 = (v2 > 0.0f) ? v2 + 1.0f : expf(v2);
                v3 = (v3 > 0.0f) ? v3 + 1.0f : expf(v3);
            }
            if (RND) {
                v0 = tf32_rna(v0); v1 = tf32_rna(v1);
                v2 = tf32_rna(v2); v3 = tf32_rna(v3);
            }
            *(float2*)(Cb + (long)r0 * Ndim + nb) = make_float2(v0, v1);
            *(float2*)(Cb + (long)r1 * Ndim + nb) = make_float2(v2, v3);
        }
    }
}

// ---------------------------------------------------------------------------
__global__ void round_kernel(const float* __restrict__ src, float* __restrict__ dst,
                             int n4)
{
    int stride = gridDim.x * blockDim.x;
    for (int i = blockIdx.x * blockDim.x + threadIdx.x; i < n4; i += stride) {
        float4 v = ((const float4*)src)[i];
        v.x = tf32_rna(v.x); v.y = tf32_rna(v.y);
        v.z = tf32_rna(v.z); v.w = tf32_rna(v.w);
        ((float4*)dst)[i] = v;
    }
}

// Ksum from Kt layout [b][d][n]: contiguous row sum. One warp per (b,d).
__global__ void ksum_row_kernel(const float* __restrict__ Kt, float* __restrict__ Ks)
{
    int r    = blockIdx.x * 8 + (threadIdx.x >> 5);   // 0..8191 = b*1024+d
    int lane = threadIdx.x & 31;
    const float4* p = (const float4*)(Kt + (long)r * NSEQ);
    float s = 0.0f;
    #pragma unroll
    for (int i = lane; i < NSEQ / 4; i += 32) {
        float4 v = p[i];
        s += v.x + v.y + v.z + v.w;
    }
    #pragma unroll
    for (int o = 16; o; o >>= 1) s += __shfl_xor_sync(0xffffffffu, s, o);
    if (lane == 0) Ks[r] = s;
}

// Z[b,n] = Q[b,n,:] . (Ksum[b,:] + 1e-6)
__global__ void z_kernel(const float* __restrict__ Q, const float* __restrict__ Ks,
                         float* __restrict__ Z)
{
    int row  = blockIdx.x * 8 + (threadIdx.x >> 5);
    int lane = threadIdx.x & 31;
    int b    = row >> 12;
    const float4* q  = (const float4*)(Q + (long)row * DIM);
    const float4* ks = (const float4*)(Ks + b * DIM);
    float s = 0.0f;
    #pragma unroll
    for (int i = lane; i < DIM / 4; i += 32) {
        float4 qv = q[i];
        float4 kv = ks[i];
        s += qv.x * (kv.x + 1e-6f) + qv.y * (kv.y + 1e-6f)
           + qv.z * (kv.z + 1e-6f) + qv.w * (kv.w + 1e-6f);
    }
    #pragma unroll
    for (int o = 16; o; o >>= 1) s += __shfl_xor_sync(0xffffffffu, s, o);
    if (lane == 0) Z[row] = s;
}

// ---------------------------------------------------------------------------
extern "C" void kernel_launch(void* const* d_in, const int* in_sizes, int n_in,
                              void* d_out, int out_size)
{
    const float* x  = (const float*)d_in[0];
    const float* Wq = (const float*)d_in[1];
    const float* bq = (const float*)d_in[2];
    const float* Wk = (const float*)d_in[3];
    const float* bk = (const float*)d_in[4];
    const float* Wv = (const float*)d_in[5];
    const float* bv = (const float*)d_in[6];
    const float* Wo = (const float*)d_in[7];
    const float* bo = (const float*)d_in[8];
    float* out = (float*)d_out;

    float *X, *RWq, *RWk, *RWv, *RWo, *Q, *Kt, *Vt, *KV, *Mt, *Ks, *Z;
    cudaGetSymbolAddress((void**)&X,   g_X);
    cudaGetSymbolAddress((void**)&RWq, g_Wq);
    cudaGetSymbolAddress((void**)&RWk, g_Wk);
    cudaGetSymbolAddress((void**)&RWv, g_Wv);
    cudaGetSymbolAddress((void**)&RWo, g_Wo);
    cudaGetSymbolAddress((void**)&Q,   g_Q);
    cudaGetSymbolAddress((void**)&Kt,  g_Kt);
    cudaGetSymbolAddress((void**)&Vt,  g_Vt);
    cudaGetSymbolAddress((void**)&KV,  g_KV);
    cudaGetSymbolAddress((void**)&Mt,  g_Mt);
    cudaGetSymbolAddress((void**)&Ks,  g_Ksum);
    cudaGetSymbolAddress((void**)&Z,   g_Z);

    const int MQ = BATCH * NSEQ;        // 32768
    dim3 blk(256);

    // 0) RNA prepass
    round_kernel<<<2048, blk>>>(x,  X,   (MQ * DIM) / 4);
    round_kernel<<<256,  blk>>>(Wq, RWq, (DIM * DIM) / 4);
    round_kernel<<<256,  blk>>>(Wk, RWk, (DIM * DIM) / 4);
    round_kernel<<<256,  blk>>>(Wv, RWv, (DIM * DIM) / 4);
    round_kernel<<<256,  blk>>>(Wo, RWo, (DIM * DIM) / 4);

    // 1) Q[n,d] = elu(X @ Wq^T + bq)+1    (col-bias+elu)
    gemm_tf32<1, 1><<<dim3(DIM / TBN, MQ / TBM, 1), blk>>>(
        X, RWq, bq, nullptr, Q, DIM, DIM, 0, 0, 0, 0);

    // 2) Kt[d,n] = elu(Wk @ X^T + bk[row])+1   (row-bias+elu), per batch
    gemm_tf32<5, 1><<<dim3(NSEQ / TBN, DIM / TBM, BATCH), blk>>>(
        RWk, X, bk, nullptr, Kt, NSEQ, DIM,
        0, (long)NSEQ * DIM, (long)DIM * NSEQ, 0);

    // 3) Vt[e,n] = Wv @ X^T + bv[row]          (row-bias), per batch
    gemm_tf32<4, 1><<<dim3(NSEQ / TBN, DIM / TBM, BATCH), blk>>>(
        RWv, X, bv, nullptr, Vt, NSEQ, DIM,
        0, (long)NSEQ * DIM, (long)DIM * NSEQ, 0);

    // 4) Ksum: contiguous row sums of Kt
    ksum_row_kernel<<<(BATCH * DIM) / 8, blk>>>(Kt, Ks);

    // 5) KV[d,e] = sum_n Kt[d,n] Vt[e,n]   (k = 4096)
    gemm_tf32<3, 1><<<dim3(DIM / TBN, DIM / TBM, BATCH), blk>>>(
        Kt, Vt, nullptr, nullptr, KV, DIM, NSEQ,
        (long)DIM * NSEQ, (long)DIM * NSEQ, (long)DIM * DIM, 0);

    // 6) Mt[e,d] = sum_c Wo[e,c] KV[d,c]
    gemm_tf32<3, 1><<<dim3(DIM / TBN, DIM / TBM, BATCH), blk>>>(
        RWo, KV, nullptr, nullptr, Mt, DIM, DIM,
        0, (long)DIM * DIM, (long)DIM * DIM, 0);

    // 7) Z
    z_kernel<<<MQ / 8, blk>>>(Q, Ks, Z);

    // 8) out[n,e] = (Q @ Mt^T)/Z + bo
    gemm_tf32<2, 0><<<dim3(DIM / TBN, NSEQ / TBM, BATCH), blk>>>(
        Q, Mt, bo, Z, out, DIM, DIM,
        (long)NSEQ * DIM, (long)DIM * DIM, (long)NSEQ * DIM, NSEQ);
}